// round 14
// baseline (speedup 1.0000x reference)
#include <cuda_runtime.h>
#include <cuda_fp16.h>
#include <cstdint>

#define BB 4
#define CC 256
#define NN 4096
#define DD 32
#define EPSBN 1e-5f

// Scratch (device globals; no allocation)
__device__ __align__(16) __half g_xth[BB * NN * CC];   // x^T hi [b][n][c]
__device__ __align__(16) __half g_xtl[BB * NN * CC];   // x^T lo
__device__ __align__(16) __half g_wvh[CC * CC];        // w_v hi [o][c]
__device__ __align__(16) __half g_wvl[CC * CC];
__device__ __align__(16) __half g_wqkh[64 * CC];       // rows 0..31 wq, 32..63 wk
__device__ __align__(16) __half g_wqkl[64 * CC];
// fp16 flash inputs
__device__ __align__(16) __half g_qfh[BB * NN * DD];   // [b][n][d]
__device__ __align__(16) __half g_qfl[BB * NN * DD];
__device__ __align__(16) __half g_kfh[BB * NN * DD];   // [b][n][d]
__device__ __align__(16) __half g_kfl[BB * NN * DD];
__device__ __align__(16) __half g_vf [BB * CC * NN];   // [b][c][n]

// ===========================================================================
// Helpers
// ===========================================================================
__device__ __forceinline__ void h_split(float y, __half& h, __half& l) {
    h = __float2half_rn(y);
    l = __float2half_rn(y - __half2float(h));
}
__device__ __forceinline__ void cpasync16(uint32_t dst, const void* src) {
    asm volatile("cp.async.cg.shared.global [%0], [%1], 16;" :: "r"(dst), "l"(src));
}
#define CP_COMMIT() asm volatile("cp.async.commit_group;" ::: "memory")
#define CP_WAIT0()  asm volatile("cp.async.wait_group 0;" ::: "memory")
__device__ __forceinline__ uint32_t smem_u32(const void* p) {
    uint32_t a;
    asm("{ .reg .u64 t; cvta.to.shared.u64 t, %1; cvt.u32.u64 %0, t; }" : "=r"(a) : "l"(p));
    return a;
}
__device__ __forceinline__ void mma_f16(float* d,
                                        uint32_t a0, uint32_t a1, uint32_t a2, uint32_t a3,
                                        uint32_t b0, uint32_t b1) {
    asm volatile(
        "mma.sync.aligned.m16n8k16.row.col.f32.f16.f16.f32 "
        "{%0,%1,%2,%3}, {%4,%5,%6,%7}, {%8,%9}, {%0,%1,%2,%3};"
        : "+f"(d[0]), "+f"(d[1]), "+f"(d[2]), "+f"(d[3])
        : "r"(a0), "r"(a1), "r"(a2), "r"(a3), "r"(b0), "r"(b1));
}
__device__ __forceinline__ void ldsm_x4(uint32_t& r0, uint32_t& r1,
                                        uint32_t& r2, uint32_t& r3, uint32_t addr) {
    asm volatile("ldmatrix.sync.aligned.m8n8.x4.shared.b16 {%0,%1,%2,%3}, [%4];"
                 : "=r"(r0), "=r"(r1), "=r"(r2), "=r"(r3) : "r"(addr));
}

// ===========================================================================
// split_xt: x [b][c][n] fp32 -> x^T hi/lo fp16 [b][n][c]. Tiled transpose.
// ===========================================================================
__global__ __launch_bounds__(256) void split_xt_kernel(const float* __restrict__ x) {
    __shared__ __half shh[64][65];
    __shared__ __half shl[64][65];
    const int b  = blockIdx.z;
    const int c0 = blockIdx.y * 64;
    const int n0 = blockIdx.x * 64;
    const int tid = threadIdx.x;
    {
        int c = tid >> 2, ng = tid & 3;
#pragma unroll
        for (int i = 0; i < 4; i++) {
            int n = ng * 16 + i * 4;
            float4 v = *reinterpret_cast<const float4*>(
                x + (size_t)(b * CC + c0 + c) * NN + n0 + n);
            h_split(v.x, shh[c][n + 0], shl[c][n + 0]);
            h_split(v.y, shh[c][n + 1], shl[c][n + 1]);
            h_split(v.z, shh[c][n + 2], shl[c][n + 2]);
            h_split(v.w, shh[c][n + 3], shl[c][n + 3]);
        }
    }
    __syncthreads();
    {
        int n = tid >> 2, cg = tid & 3;
        __half bh[16], bl[16];
#pragma unroll
        for (int j = 0; j < 16; j++) {
            bh[j] = shh[cg * 16 + j][n];
            bl[j] = shl[cg * 16 + j][n];
        }
        size_t base = (size_t)(b * NN + n0 + n) * CC + c0 + cg * 16;
        reinterpret_cast<uint4*>(g_xth + base)[0] = reinterpret_cast<uint4*>(bh)[0];
        reinterpret_cast<uint4*>(g_xth + base)[1] = reinterpret_cast<uint4*>(bh)[1];
        reinterpret_cast<uint4*>(g_xtl + base)[0] = reinterpret_cast<uint4*>(bl)[0];
        reinterpret_cast<uint4*>(g_xtl + base)[1] = reinterpret_cast<uint4*>(bl)[1];
    }
}

// ===========================================================================
// split_w_f16: weights -> fp16 hi/lo.
// ===========================================================================
__global__ __launch_bounds__(256) void split_w_f16_kernel(
    const float* __restrict__ w_q, const float* __restrict__ w_k,
    const float* __restrict__ w_v)
{
    int idx = blockIdx.x * 256 + threadIdx.x;
    if (idx < CC * CC) {
        __half h, l; h_split(w_v[idx], h, l);
        g_wvh[idx] = h; g_wvl[idx] = l;
    } else {
        int j = idx - CC * CC;
        int o = j >> 8, c = j & 255;
        float v = (o < 32) ? w_q[o * CC + c] : w_k[(o - 32) * CC + c];
        __half h, l; h_split(v, h, l);
        g_wqkh[j] = h; g_wqkl[j] = l;
    }
}

// ===========================================================================
// qk projection, fp16 3-term compensated mma. (unchanged from R13)
// ===========================================================================
#define QKP_SMB 102400

__global__ __launch_bounds__(256, 1) void qk_proj_f16_kernel(
    const float* __restrict__ s1, const float* __restrict__ b1,
    const float* __restrict__ m1, const float* __restrict__ v1,
    const float* __restrict__ s2, const float* __restrict__ b2,
    const float* __restrict__ m2, const float* __restrict__ v2)
{
    extern __shared__ char smc[];
    const uint32_t sb = smem_u32(smc);
    const uint32_t* su = reinterpret_cast<const uint32_t*>(smc);
    __half* st = reinterpret_cast<__half*>(smc);

    const int b  = blockIdx.y;
    const int n0 = blockIdx.x * 256;
    const int tid = threadIdx.x;
    const int w = tid >> 5, lane = tid & 31;
    const int r = lane >> 2, q = lane & 3;

#define QKF_FILL(kc, bf) do { \
        const uint32_t bo = (bf) * 51200u; \
        _Pragma("unroll") \
        for (int t = 0; t < 10; t++) { \
            int idx = tid + (t << 8); \
            if (idx < 512) { \
                int arr = idx >> 8, j = idx & 255; \
                int row = j >> 2, ck = j & 3; \
                const __half* src = (arr ? g_wqkl : g_wqkh) + row * CC + (kc) + ck * 8; \
                cpasync16(sb + bo + arr * 5120u + row * 80 + ck * 16, src); \
            } else { \
                int j = idx - 512; \
                int arr = j >> 10; j &= 1023; \
                int row = j >> 2, ck = j & 3; \
                const __half* src = (arr ? g_xtl : g_xth) \
                    + (size_t)(b * NN + n0 + row) * CC + (kc) + ck * 8; \
                cpasync16(sb + bo + 10240u + arr * 20480u + row * 80 + ck * 16, src); \
            } \
        } \
        CP_COMMIT(); \
    } while (0)

    QKF_FILL(0, 0);

    float acc[4][4][4];
#pragma unroll
    for (int mf = 0; mf < 4; mf++)
#pragma unroll
        for (int nf = 0; nf < 4; nf++)
#pragma unroll
            for (int e = 0; e < 4; e++) acc[mf][nf][e] = 0.f;

    for (int ch = 0; ch < 8; ch++) {
        CP_WAIT0();
        __syncthreads();
        if (ch + 1 < 8) QKF_FILL((ch + 1) * 32, (ch + 1) & 1);
        const int bw = (ch & 1) * 12800;

#pragma unroll
        for (int ks = 0; ks < 2; ks++) {
            uint32_t bh[4][2], bl[4][2];
#pragma unroll
            for (int nf = 0; nf < 4; nf++) {
                int na = bw + 2560 + (w * 32 + nf * 8 + r) * 20 + ks * 8 + q;
                bh[nf][0] = su[na];        bh[nf][1] = su[na + 4];
                bl[nf][0] = su[na + 5120]; bl[nf][1] = su[na + 5124];
            }
#pragma unroll
            for (int mf = 0; mf < 4; mf++) {
                int aa = bw + (mf * 16 + r) * 20 + ks * 8 + q;
                uint32_t ah0 = su[aa], ah1 = su[aa + 160];
                uint32_t ah2 = su[aa + 4], ah3 = su[aa + 164];
                uint32_t al0 = su[aa + 1280], al1 = su[aa + 1440];
                uint32_t al2 = su[aa + 1284], al3 = su[aa + 1444];
#pragma unroll
                for (int nf = 0; nf < 4; nf++) {
                    mma_f16(acc[mf][nf], ah0, ah1, ah2, ah3, bh[nf][0], bh[nf][1]);
                    mma_f16(acc[mf][nf], ah0, ah1, ah2, ah3, bl[nf][0], bl[nf][1]);
                    mma_f16(acc[mf][nf], al0, al1, al2, al3, bh[nf][0], bh[nf][1]);
                }
            }
        }
        __syncthreads();
    }

#pragma unroll
    for (int mf = 0; mf < 4; mf++) {
        const int isK = mf >> 1;
#pragma unroll
        for (int er = 0; er < 2; er++) {
            const int d = (mf & 1) * 16 + er * 8 + r;
            float iv, off;
            if (!isK) { iv = s1[d] * rsqrtf(v1[d] + EPSBN); off = b1[d] - m1[d] * iv; }
            else      { iv = s2[d] * rsqrtf(v2[d] + EPSBN); off = b2[d] - m2[d] * iv; }
            const int hb = isK ? 16384 : 0;
#pragma unroll
            for (int nf = 0; nf < 4; nf++) {
                const int n = w * 32 + nf * 8 + 2 * q;
                float y0 = fmaxf(fmaf(acc[mf][nf][er * 2 + 0], iv, off), 0.f);
                float y1 = fmaxf(fmaf(acc[mf][nf][er * 2 + 1], iv, off), 0.f);
                __half h0, l0, h1, l1;
                h_split(y0, h0, l0);
                h_split(y1, h1, l1);
                st[hb + n * 32 + d] = h0;        st[hb + (n + 1) * 32 + d] = h1;
                st[hb + 8192 + n * 32 + d] = l0; st[hb + 8192 + (n + 1) * 32 + d] = l1;
            }
        }
    }
    __syncthreads();
    {
        __half* gp[4] = { g_qfh, g_qfl, g_kfh, g_kfl };
        const int n = tid;
#pragma unroll
        for (int arr = 0; arr < 4; arr++) {
            const uint4* src = reinterpret_cast<const uint4*>(st + arr * 8192 + n * 32);
            uint4* dst = reinterpret_cast<uint4*>(gp[arr] + (size_t)(b * NN + n0 + n) * DD);
#pragma unroll
            for (int j = 0; j < 4; j++) dst[j] = src[j];
        }
    }
#undef QKF_FILL
}

// ===========================================================================
// v projection, fp16 3-term compensated mma. (unchanged from R13)
// ===========================================================================
#define VP_SMB 122880

__global__ __launch_bounds__(256, 1) void v_proj_f16_kernel(
    const float* __restrict__ s3, const float* __restrict__ b3,
    const float* __restrict__ m3, const float* __restrict__ v3)
{
    extern __shared__ char smc[];
    const uint32_t sb = smem_u32(smc);
    const uint32_t* su = reinterpret_cast<const uint32_t*>(smc);

    const int b  = blockIdx.y;
    const int n0 = blockIdx.x * 128;
    const int tid = threadIdx.x;
    const int w = tid >> 5, lane = tid & 31;
    const int wo = w >> 2, wn = w & 3;
    const int r = lane >> 2, q = lane & 3;

#define VF_FILL(kc, bf) do { \
        const uint32_t bo = (bf) * 61440u; \
        _Pragma("unroll") \
        for (int t = 0; t < 12; t++) { \
            int idx = tid + (t << 8); \
            if (idx < 2048) { \
                int arr = idx >> 10, j = idx & 1023; \
                int row = j >> 2, ck = j & 3; \
                const __half* src = (arr ? g_wvl : g_wvh) + row * CC + (kc) + ck * 8; \
                cpasync16(sb + bo + arr * 20480u + row * 80 + ck * 16, src); \
            } else { \
                int j = idx - 2048; \
                int arr = j >> 9; j &= 511; \
                int row = j >> 2, ck = j & 3; \
                const __half* src = (arr ? g_xtl : g_xth) \
                    + (size_t)(b * NN + n0 + row) * CC + (kc) + ck * 8; \
                cpasync16(sb + bo + 40960u + arr * 10240u + row * 80 + ck * 16, src); \
            } \
        } \
        CP_COMMIT(); \
    } while (0)

    VF_FILL(0, 0);

    float acc[8][4][4];
#pragma unroll
    for (int mf = 0; mf < 8; mf++)
#pragma unroll
        for (int nf = 0; nf < 4; nf++)
#pragma unroll
            for (int e = 0; e < 4; e++) acc[mf][nf][e] = 0.f;

    for (int ch = 0; ch < 8; ch++) {
        CP_WAIT0();
        __syncthreads();
        if (ch + 1 < 8) VF_FILL((ch + 1) * 32, (ch + 1) & 1);
        const int bw = (ch & 1) * 15360;

#pragma unroll
        for (int ks = 0; ks < 2; ks++) {
            uint32_t bh[4][2], bl[4][2];
#pragma unroll
            for (int nf = 0; nf < 4; nf++) {
                int na = bw + 10240 + (wn * 32 + nf * 8 + r) * 20 + ks * 8 + q;
                bh[nf][0] = su[na];        bh[nf][1] = su[na + 4];
                bl[nf][0] = su[na + 2560]; bl[nf][1] = su[na + 2564];
            }
#pragma unroll
            for (int mf = 0; mf < 8; mf++) {
                int aa = bw + (wo * 128 + mf * 16 + r) * 20 + ks * 8 + q;
                uint32_t ah0 = su[aa], ah1 = su[aa + 160];
                uint32_t ah2 = su[aa + 4], ah3 = su[aa + 164];
                uint32_t al0 = su[aa + 5120], al1 = su[aa + 5280];
                uint32_t al2 = su[aa + 5124], al3 = su[aa + 5284];
#pragma unroll
                for (int nf = 0; nf < 4; nf++) {
                    mma_f16(acc[mf][nf], ah0, ah1, ah2, ah3, bh[nf][0], bh[nf][1]);
                    mma_f16(acc[mf][nf], ah0, ah1, ah2, ah3, bl[nf][0], bl[nf][1]);
                    mma_f16(acc[mf][nf], al0, al1, al2, al3, bh[nf][0], bh[nf][1]);
                }
            }
        }
        __syncthreads();
    }

#pragma unroll
    for (int mf = 0; mf < 8; mf++) {
#pragma unroll
        for (int er = 0; er < 2; er++) {
            const int c = wo * 128 + mf * 16 + er * 8 + r;
            float iv = s3[c] * rsqrtf(v3[c] + EPSBN);
            float off = b3[c] - m3[c] * iv;
#pragma unroll
            for (int nf = 0; nf < 4; nf++) {
                const int n = n0 + wn * 32 + nf * 8 + 2 * q;
                float y0 = fmaxf(fmaf(acc[mf][nf][er * 2 + 0], iv, off), 0.f);
                float y1 = fmaxf(fmaf(acc[mf][nf][er * 2 + 1], iv, off), 0.f);
                *reinterpret_cast<__half2*>(&g_vf[(size_t)(b * CC + c) * NN + n]) =
                    __floats2half2_rn(y0, y1);
            }
        }
    }
#undef VF_FILL
}

// ===========================================================================
// Flash attention fp16, 512 threads (16 warps), ldmatrix fragment loads.
// Warp: row-group g = w>>1 (16 rows), c-half = w&1 (128 c). Phase A duplicated
// per c-half pair; softmax state warp-local. grid (32, 4), one wave.
// Smem: QH[128][80]=10240, QL=10240, KH[32][80]x2=5120, KL=5120, V[256][80]x2=40960.
// ===========================================================================
#define SQH 0
#define SQL 10240
#define SKH 20480
#define SKL 25600
#define SV  30720
#define FL_BYTES 71680

__global__ __launch_bounds__(512, 1)
void flash_f16_kernel(const float* __restrict__ x,
                      const float* __restrict__ gamma_p,
                      float* __restrict__ out)
{
    extern __shared__ char smc[];
    const uint32_t sb = smem_u32(smc);
    const uint32_t* qhw = reinterpret_cast<const uint32_t*>(smc + SQH);
    const uint32_t* qlw = reinterpret_cast<const uint32_t*>(smc + SQL);

    const int b   = blockIdx.y;
    const int i0  = blockIdx.x * 128;
    const int tid = threadIdx.x;
    const int w    = tid >> 5;
    const int lane = tid & 31;
    const int r    = lane >> 2;
    const int q    = lane & 3;
    const int g    = w >> 1;            // row group 0..7
    const int cb   = (w & 1) << 7;      // c base 0/128
    const int row  = g * 16 + r;

    // ldmatrix lane geometry: matrix idx = lane>>3; rows split by (lane>>4).
    const int lrow = ((lane >> 4) << 3) + (lane & 7);
    const int lko4 = ((lane >> 3) & 1) << 4;   // byte offset for k-half (4 words)
    const uint32_t kAddr0 = sb + SKH + (uint32_t)lrow * 80 + lko4;   // +5120 for lo
    const uint32_t vAddr0 = sb + SV + (uint32_t)(cb + lrow) * 80 + lko4;

#define FILL_KV(j0_, bf_) do { \
        if (tid < 256) { \
            int split = tid >> 7, rem = tid & 127; \
            int j = rem >> 2, ck = rem & 3; \
            const __half* src = (split ? g_kfl : g_kfh) + (size_t)(b * NN + (j0_) + j) * DD + ck * 8; \
            cpasync16(sb + (split ? SKL : SKH) + (bf_) * 2560 + j * 80 + ck * 16, src); } \
        _Pragma("unroll") \
        for (int tt = 0; tt < 2; tt++) { \
            int idx = tid + (tt << 9); \
            int c = idx >> 2, ck = idx & 3; \
            const __half* src = g_vf + (size_t)(b * CC + c) * NN + (j0_) + ck * 8; \
            cpasync16(sb + SV + (bf_) * 20480 + c * 80 + ck * 16, src); } \
    } while (0)

    // Prologue: Q hi/lo [128][32]
    {
        const __half* qh = g_qfh + (size_t)(b * NN + i0) * DD;
        const __half* ql = g_qfl + (size_t)(b * NN + i0) * DD;
        int m = tid >> 2, ck = tid & 3;
        cpasync16(sb + SQH + m * 80 + ck * 16, qh + m * DD + ck * 8);
        cpasync16(sb + SQL + m * 80 + ck * 16, ql + m * DD + ck * 8);
    }
    FILL_KV(0, 0);
    CP_COMMIT();
    CP_WAIT0();
    __syncthreads();

    // Q-hi fragments in registers (iter-invariant); Q-lo reloaded per iter.
    uint32_t qa[2][4];
#pragma unroll
    for (int ch = 0; ch < 2; ch++) {
        int off = row * 20 + q + ch * 8;
        qa[ch][0] = qhw[off];       qa[ch][1] = qhw[off + 160];
        qa[ch][2] = qhw[off + 4];   qa[ch][3] = qhw[off + 164];
    }

    float oacc[16][4];
#pragma unroll
    for (int ct = 0; ct < 16; ct++)
#pragma unroll
        for (int e = 0; e < 4; e++) oacc[ct][e] = 0.f;
    float M0 = -1e30f, M1 = -1e30f, l0 = 0.f, l1 = 0.f;

    for (int t = 0; t < 128; t++) {
        const uint32_t kbf = (t & 1) * 2560;
        const uint32_t vbf = (t & 1) * 20480;

        if (t > 0) { CP_WAIT0(); __syncthreads(); }
        if (t + 1 < 128) { FILL_KV((t + 1) * 32, (t + 1) & 1); CP_COMMIT(); }

        // ---- Phase A: S[row..+16][0..32), 3-term fp16 compensation ----
        float sacc[4][4];
#pragma unroll
        for (int jt = 0; jt < 4; jt++)
#pragma unroll
            for (int e = 0; e < 4; e++) sacc[jt][e] = 0.f;

#pragma unroll
        for (int ch = 0; ch < 2; ch++) {
            // Q-lo fragment for this k-half (reloaded from smem)
            int qoff = row * 20 + q + ch * 8;
            uint32_t qb0 = qlw[qoff], qb1 = qlw[qoff + 160];
            uint32_t qb2 = qlw[qoff + 4], qb3 = qlw[qoff + 164];
#pragma unroll
            for (int jt0 = 0; jt0 < 4; jt0 += 2) {
                uint32_t kh0, kh1, kh2, kh3, kl0, kl1, kl2, kl3;
                uint32_t ka = kAddr0 + kbf + (uint32_t)jt0 * 640 + ch * 32;
                ldsm_x4(kh0, kh1, kh2, kh3, ka);
                ldsm_x4(kl0, kl1, kl2, kl3, ka + 5120);
                mma_f16(sacc[jt0],     qa[ch][0], qa[ch][1], qa[ch][2], qa[ch][3], kh0, kh1);
                mma_f16(sacc[jt0],     qa[ch][0], qa[ch][1], qa[ch][2], qa[ch][3], kl0, kl1);
                mma_f16(sacc[jt0],     qb0, qb1, qb2, qb3, kh0, kh1);
                mma_f16(sacc[jt0 + 1], qa[ch][0], qa[ch][1], qa[ch][2], qa[ch][3], kh2, kh3);
                mma_f16(sacc[jt0 + 1], qa[ch][0], qa[ch][1], qa[ch][2], qa[ch][3], kl2, kl3);
                mma_f16(sacc[jt0 + 1], qb0, qb1, qb2, qb3, kh2, kh3);
            }
        }

        // ---- Online row max (warp-local) ----
        float mx0 = fmaxf(fmaxf(sacc[0][0], sacc[0][1]), fmaxf(sacc[1][0], sacc[1][1]));
        mx0 = fmaxf(mx0, fmaxf(fmaxf(sacc[2][0], sacc[2][1]), fmaxf(sacc[3][0], sacc[3][1])));
        float mx1 = fmaxf(fmaxf(sacc[0][2], sacc[0][3]), fmaxf(sacc[1][2], sacc[1][3]));
        mx1 = fmaxf(mx1, fmaxf(fmaxf(sacc[2][2], sacc[2][3]), fmaxf(sacc[3][2], sacc[3][3])));
        mx0 = fmaxf(mx0, __shfl_xor_sync(0xFFFFFFFFu, mx0, 1));
        mx0 = fmaxf(mx0, __shfl_xor_sync(0xFFFFFFFFu, mx0, 2));
        mx1 = fmaxf(mx1, __shfl_xor_sync(0xFFFFFFFFu, mx1, 1));
        mx1 = fmaxf(mx1, __shfl_xor_sync(0xFFFFFFFFu, mx1, 2));
        float nm0 = fmaxf(M0, mx0), nm1 = fmaxf(M1, mx1);
        bool chg = (nm0 != M0) || (nm1 != M1);
        if (__any_sync(0xFFFFFFFFu, chg)) {
            float al0 = __expf(M0 - nm0), al1 = __expf(M1 - nm1);
            M0 = nm0; M1 = nm1;
            l0 *= al0; l1 *= al1;
#pragma unroll
            for (int ct = 0; ct < 16; ct++) {
                oacc[ct][0] *= al0; oacc[ct][1] *= al0;
                oacc[ct][2] *= al1; oacc[ct][3] *= al1;
            }
        }

        // ---- exp -> fp16 P fragments (registers), l partials ----
        uint32_t aP[2][4];
#pragma unroll
        for (int jc = 0; jc < 2; jc++) {
            const int t0 = 2 * jc, t1 = 2 * jc + 1;
            __half2 h0 = __floats2half2_rn(__expf(sacc[t0][0] - M0), __expf(sacc[t0][1] - M0));
            __half2 h1 = __floats2half2_rn(__expf(sacc[t0][2] - M1), __expf(sacc[t0][3] - M1));
            __half2 h2 = __floats2half2_rn(__expf(sacc[t1][0] - M0), __expf(sacc[t1][1] - M0));
            __half2 h3 = __floats2half2_rn(__expf(sacc[t1][2] - M1), __expf(sacc[t1][3] - M1));
            float2 f0 = __half22float2(h0), f1 = __half22float2(h1);
            float2 f2 = __half22float2(h2), f3 = __half22float2(h3);
            l0 += f0.x + f0.y + f2.x + f2.y;
            l1 += f1.x + f1.y + f3.x + f3.y;
            aP[jc][0] = *reinterpret_cast<uint32_t*>(&h0);
            aP[jc][1] = *reinterpret_cast<uint32_t*>(&h1);
            aP[jc][2] = *reinterpret_cast<uint32_t*>(&h2);
            aP[jc][3] = *reinterpret_cast<uint32_t*>(&h3);
        }

        // ---- Phase B: O[row..+16][cb..+128) += P * V (ldmatrix x4) ----
#pragma unroll
        for (int jc = 0; jc < 2; jc++) {
#pragma unroll
            for (int ct0 = 0; ct0 < 16; ct0 += 2) {
                uint32_t v0, v1, v2, v3;
                ldsm_x4(v0, v1, v2, v3, vAddr0 + vbf + (uint32_t)ct0 * 640 + jc * 32);
                mma_f16(oacc[ct0],     aP[jc][0], aP[jc][1], aP[jc][2], aP[jc][3], v0, v1);
                mma_f16(oacc[ct0 + 1], aP[jc][0], aP[jc][1], aP[jc][2], aP[jc][3], v2, v3);
            }
        }
    }

    // ---- Final l reduction across quad lanes ----
    l0 += __shfl_xor_sync(0xFFFFFFFFu, l0, 1);
    l0 += __shfl_xor_sync(0xFFFFFFFFu, l0, 2);
    l1 += __shfl_xor_sync(0xFFFFFFFFu, l1, 1);
    l1 += __shfl_xor_sync(0xFFFFFFFFu, l1, 2);

    const float gam = gamma_p[0];
    const float s0 = gam / l0, s1 = gam / l1;
    const int mrow0 = i0 + row;
    const int mrow1 = mrow0 + 8;
#pragma unroll
    for (int ct = 0; ct < 16; ct++) {
        const int c0 = cb + ct * 8 + 2 * q;
        size_t g00 = (size_t)(b * CC + c0) * NN + mrow0;
        size_t g01 = (size_t)(b * CC + c0 + 1) * NN + mrow0;
        size_t g10 = (size_t)(b * CC + c0) * NN + mrow1;
        size_t g11 = (size_t)(b * CC + c0 + 1) * NN + mrow1;
        out[g00] = fmaf(oacc[ct][0], s0, x[g00]);
        out[g01] = fmaf(oacc[ct][1], s0, x[g01]);
        out[g10] = fmaf(oacc[ct][2], s1, x[g10]);
        out[g11] = fmaf(oacc[ct][3], s1, x[g11]);
    }
#undef FILL_KV
}

// ===========================================================================
extern "C" void kernel_launch(void* const* d_in, const int* in_sizes, int n_in,
                              void* d_out, int out_size)
{
    const float* x   = (const float*)d_in[0];
    const float* w_q = (const float*)d_in[1];
    const float* w_k = (const float*)d_in[2];
    const float* w_v = (const float*)d_in[3];
    const float* s1 = (const float*)d_in[4];
    const float* b1 = (const float*)d_in[5];
    const float* m1 = (const float*)d_in[6];
    const float* v1 = (const float*)d_in[7];
    const float* s2 = (const float*)d_in[8];
    const float* b2 = (const float*)d_in[9];
    const float* m2 = (const float*)d_in[10];
    const float* v2 = (const float*)d_in[11];
    const float* s3 = (const float*)d_in[12];
    const float* b3 = (const float*)d_in[13];
    const float* m3 = (const float*)d_in[14];
    const float* v3 = (const float*)d_in[15];
    const float* gamma = (const float*)d_in[16];
    float* out = (float*)d_out;

    cudaFuncSetAttribute(qk_proj_f16_kernel, cudaFuncAttributeMaxDynamicSharedMemorySize, QKP_SMB);
    cudaFuncSetAttribute(v_proj_f16_kernel,  cudaFuncAttributeMaxDynamicSharedMemorySize, VP_SMB);
    cudaFuncSetAttribute(flash_f16_kernel,   cudaFuncAttributeMaxDynamicSharedMemorySize, FL_BYTES);

    split_xt_kernel<<<dim3(NN / 64, CC / 64, BB), 256>>>(x);
    split_w_f16_kernel<<<(CC * CC + 64 * CC) / 256, 256>>>(w_q, w_k, w_v);
    qk_proj_f16_kernel<<<dim3(NN / 256, BB), 256, QKP_SMB>>>(
        s1, b1, m1, v1, s2, b2, m2, v2);
    v_proj_f16_kernel<<<dim3(NN / 128, BB), 256, VP_SMB>>>(s3, b3, m3, v3);
    flash_f16_kernel<<<dim3(NN / 128, BB), 512, FL_BYTES>>>(x, gamma, out);
}

// round 16
// speedup vs baseline: 1.3120x; 1.3120x over previous
#include <cuda_runtime.h>
#include <cuda_fp16.h>
#include <cstdint>

#define BB 4
#define CC 256
#define NN 4096
#define DD 32
#define EPSBN 1e-5f

// Scratch (device globals; no allocation)
__device__ __align__(16) __half g_xth[BB * NN * CC];   // x^T hi [b][n][c]
__device__ __align__(16) __half g_xtl[BB * NN * CC];   // x^T lo
__device__ __align__(16) __half g_wvh[CC * CC];        // w_v hi [o][c]
__device__ __align__(16) __half g_wvl[CC * CC];
__device__ __align__(16) __half g_wqkh[64 * CC];       // rows 0..31 wq, 32..63 wk
__device__ __align__(16) __half g_wqkl[64 * CC];
// fp16 flash inputs
__device__ __align__(16) __half g_qfh[BB * NN * DD];   // [b][n][d]
__device__ __align__(16) __half g_qfl[BB * NN * DD];
__device__ __align__(16) __half g_kfh[BB * NN * DD];   // [b][n][d]
__device__ __align__(16) __half g_kfl[BB * NN * DD];
__device__ __align__(16) __half g_vf [BB * CC * NN];   // [b][c][n]

// ===========================================================================
// Helpers
// ===========================================================================
__device__ __forceinline__ void h_split(float y, __half& h, __half& l) {
    h = __float2half_rn(y);
    l = __float2half_rn(y - __half2float(h));
}
__device__ __forceinline__ void cpasync16(uint32_t dst, const void* src) {
    asm volatile("cp.async.cg.shared.global [%0], [%1], 16;" :: "r"(dst), "l"(src));
}
#define CP_COMMIT() asm volatile("cp.async.commit_group;" ::: "memory")
#define CP_WAIT0()  asm volatile("cp.async.wait_group 0;" ::: "memory")
__device__ __forceinline__ uint32_t smem_u32(const void* p) {
    uint32_t a;
    asm("{ .reg .u64 t; cvta.to.shared.u64 t, %1; cvt.u32.u64 %0, t; }" : "=r"(a) : "l"(p));
    return a;
}
__device__ __forceinline__ void mma_f16(float* d,
                                        uint32_t a0, uint32_t a1, uint32_t a2, uint32_t a3,
                                        uint32_t b0, uint32_t b1) {
    asm volatile(
        "mma.sync.aligned.m16n8k16.row.col.f32.f16.f16.f32 "
        "{%0,%1,%2,%3}, {%4,%5,%6,%7}, {%8,%9}, {%0,%1,%2,%3};"
        : "+f"(d[0]), "+f"(d[1]), "+f"(d[2]), "+f"(d[3])
        : "r"(a0), "r"(a1), "r"(a2), "r"(a3), "r"(b0), "r"(b1));
}
__device__ __forceinline__ void ldsm_x4(uint32_t& r0, uint32_t& r1,
                                        uint32_t& r2, uint32_t& r3, uint32_t addr) {
    asm volatile("ldmatrix.sync.aligned.m8n8.x4.shared.b16 {%0,%1,%2,%3}, [%4];"
                 : "=r"(r0), "=r"(r1), "=r"(r2), "=r"(r3) : "r"(addr));
}

// ===========================================================================
// split_xt: x [b][c][n] fp32 -> x^T hi/lo fp16 [b][n][c]. Tiled transpose.
// ===========================================================================
__global__ __launch_bounds__(256) void split_xt_kernel(const float* __restrict__ x) {
    __shared__ __half shh[64][65];
    __shared__ __half shl[64][65];
    const int b  = blockIdx.z;
    const int c0 = blockIdx.y * 64;
    const int n0 = blockIdx.x * 64;
    const int tid = threadIdx.x;
    {
        int c = tid >> 2, ng = tid & 3;
#pragma unroll
        for (int i = 0; i < 4; i++) {
            int n = ng * 16 + i * 4;
            float4 v = *reinterpret_cast<const float4*>(
                x + (size_t)(b * CC + c0 + c) * NN + n0 + n);
            h_split(v.x, shh[c][n + 0], shl[c][n + 0]);
            h_split(v.y, shh[c][n + 1], shl[c][n + 1]);
            h_split(v.z, shh[c][n + 2], shl[c][n + 2]);
            h_split(v.w, shh[c][n + 3], shl[c][n + 3]);
        }
    }
    __syncthreads();
    {
        int n = tid >> 2, cg = tid & 3;
        __half bh[16], bl[16];
#pragma unroll
        for (int j = 0; j < 16; j++) {
            bh[j] = shh[cg * 16 + j][n];
            bl[j] = shl[cg * 16 + j][n];
        }
        size_t base = (size_t)(b * NN + n0 + n) * CC + c0 + cg * 16;
        reinterpret_cast<uint4*>(g_xth + base)[0] = reinterpret_cast<uint4*>(bh)[0];
        reinterpret_cast<uint4*>(g_xth + base)[1] = reinterpret_cast<uint4*>(bh)[1];
        reinterpret_cast<uint4*>(g_xtl + base)[0] = reinterpret_cast<uint4*>(bl)[0];
        reinterpret_cast<uint4*>(g_xtl + base)[1] = reinterpret_cast<uint4*>(bl)[1];
    }
}

// ===========================================================================
// split_w_f16: weights -> fp16 hi/lo.
// ===========================================================================
__global__ __launch_bounds__(256) void split_w_f16_kernel(
    const float* __restrict__ w_q, const float* __restrict__ w_k,
    const float* __restrict__ w_v)
{
    int idx = blockIdx.x * 256 + threadIdx.x;
    if (idx < CC * CC) {
        __half h, l; h_split(w_v[idx], h, l);
        g_wvh[idx] = h; g_wvl[idx] = l;
    } else {
        int j = idx - CC * CC;
        int o = j >> 8, c = j & 255;
        float v = (o < 32) ? w_q[o * CC + c] : w_k[(o - 32) * CC + c];
        __half h, l; h_split(v, h, l);
        g_wqkh[j] = h; g_wqkl[j] = l;
    }
}

// ===========================================================================
// qk projection, fp16 3-term compensated mma. (unchanged, proven)
// ===========================================================================
#define QKP_SMB 102400

__global__ __launch_bounds__(256, 1) void qk_proj_f16_kernel(
    const float* __restrict__ s1, const float* __restrict__ b1,
    const float* __restrict__ m1, const float* __restrict__ v1,
    const float* __restrict__ s2, const float* __restrict__ b2,
    const float* __restrict__ m2, const float* __restrict__ v2)
{
    extern __shared__ char smc[];
    const uint32_t sb = smem_u32(smc);
    const uint32_t* su = reinterpret_cast<const uint32_t*>(smc);
    __half* st = reinterpret_cast<__half*>(smc);

    const int b  = blockIdx.y;
    const int n0 = blockIdx.x * 256;
    const int tid = threadIdx.x;
    const int w = tid >> 5, lane = tid & 31;
    const int r = lane >> 2, q = lane & 3;

#define QKF_FILL(kc, bf) do { \
        const uint32_t bo = (bf) * 51200u; \
        _Pragma("unroll") \
        for (int t = 0; t < 10; t++) { \
            int idx = tid + (t << 8); \
            if (idx < 512) { \
                int arr = idx >> 8, j = idx & 255; \
                int row = j >> 2, ck = j & 3; \
                const __half* src = (arr ? g_wqkl : g_wqkh) + row * CC + (kc) + ck * 8; \
                cpasync16(sb + bo + arr * 5120u + row * 80 + ck * 16, src); \
            } else { \
                int j = idx - 512; \
                int arr = j >> 10; j &= 1023; \
                int row = j >> 2, ck = j & 3; \
                const __half* src = (arr ? g_xtl : g_xth) \
                    + (size_t)(b * NN + n0 + row) * CC + (kc) + ck * 8; \
                cpasync16(sb + bo + 10240u + arr * 20480u + row * 80 + ck * 16, src); \
            } \
        } \
        CP_COMMIT(); \
    } while (0)

    QKF_FILL(0, 0);

    float acc[4][4][4];
#pragma unroll
    for (int mf = 0; mf < 4; mf++)
#pragma unroll
        for (int nf = 0; nf < 4; nf++)
#pragma unroll
            for (int e = 0; e < 4; e++) acc[mf][nf][e] = 0.f;

    for (int ch = 0; ch < 8; ch++) {
        CP_WAIT0();
        __syncthreads();
        if (ch + 1 < 8) QKF_FILL((ch + 1) * 32, (ch + 1) & 1);
        const int bw = (ch & 1) * 12800;

#pragma unroll
        for (int ks = 0; ks < 2; ks++) {
            uint32_t bh[4][2], bl[4][2];
#pragma unroll
            for (int nf = 0; nf < 4; nf++) {
                int na = bw + 2560 + (w * 32 + nf * 8 + r) * 20 + ks * 8 + q;
                bh[nf][0] = su[na];        bh[nf][1] = su[na + 4];
                bl[nf][0] = su[na + 5120]; bl[nf][1] = su[na + 5124];
            }
#pragma unroll
            for (int mf = 0; mf < 4; mf++) {
                int aa = bw + (mf * 16 + r) * 20 + ks * 8 + q;
                uint32_t ah0 = su[aa], ah1 = su[aa + 160];
                uint32_t ah2 = su[aa + 4], ah3 = su[aa + 164];
                uint32_t al0 = su[aa + 1280], al1 = su[aa + 1440];
                uint32_t al2 = su[aa + 1284], al3 = su[aa + 1444];
#pragma unroll
                for (int nf = 0; nf < 4; nf++) {
                    mma_f16(acc[mf][nf], ah0, ah1, ah2, ah3, bh[nf][0], bh[nf][1]);
                    mma_f16(acc[mf][nf], ah0, ah1, ah2, ah3, bl[nf][0], bl[nf][1]);
                    mma_f16(acc[mf][nf], al0, al1, al2, al3, bh[nf][0], bh[nf][1]);
                }
            }
        }
        __syncthreads();
    }

#pragma unroll
    for (int mf = 0; mf < 4; mf++) {
        const int isK = mf >> 1;
#pragma unroll
        for (int er = 0; er < 2; er++) {
            const int d = (mf & 1) * 16 + er * 8 + r;
            float iv, off;
            if (!isK) { iv = s1[d] * rsqrtf(v1[d] + EPSBN); off = b1[d] - m1[d] * iv; }
            else      { iv = s2[d] * rsqrtf(v2[d] + EPSBN); off = b2[d] - m2[d] * iv; }
            const int hb = isK ? 16384 : 0;
#pragma unroll
            for (int nf = 0; nf < 4; nf++) {
                const int n = w * 32 + nf * 8 + 2 * q;
                float y0 = fmaxf(fmaf(acc[mf][nf][er * 2 + 0], iv, off), 0.f);
                float y1 = fmaxf(fmaf(acc[mf][nf][er * 2 + 1], iv, off), 0.f);
                __half h0, l0, h1, l1;
                h_split(y0, h0, l0);
                h_split(y1, h1, l1);
                st[hb + n * 32 + d] = h0;        st[hb + (n + 1) * 32 + d] = h1;
                st[hb + 8192 + n * 32 + d] = l0; st[hb + 8192 + (n + 1) * 32 + d] = l1;
            }
        }
    }
    __syncthreads();
    {
        __half* gp[4] = { g_qfh, g_qfl, g_kfh, g_kfl };
        const int n = tid;
#pragma unroll
        for (int arr = 0; arr < 4; arr++) {
            const uint4* src = reinterpret_cast<const uint4*>(st + arr * 8192 + n * 32);
            uint4* dst = reinterpret_cast<uint4*>(gp[arr] + (size_t)(b * NN + n0 + n) * DD);
#pragma unroll
            for (int j = 0; j < 4; j++) dst[j] = src[j];
        }
    }
#undef QKF_FILL
}

// ===========================================================================
// v projection, fp16 3-term compensated mma. (unchanged, proven)
// ===========================================================================
#define VP_SMB 122880

__global__ __launch_bounds__(256, 1) void v_proj_f16_kernel(
    const float* __restrict__ s3, const float* __restrict__ b3,
    const float* __restrict__ m3, const float* __restrict__ v3)
{
    extern __shared__ char smc[];
    const uint32_t sb = smem_u32(smc);
    const uint32_t* su = reinterpret_cast<const uint32_t*>(smc);

    const int b  = blockIdx.y;
    const int n0 = blockIdx.x * 128;
    const int tid = threadIdx.x;
    const int w = tid >> 5, lane = tid & 31;
    const int wo = w >> 2, wn = w & 3;
    const int r = lane >> 2, q = lane & 3;

#define VF_FILL(kc, bf) do { \
        const uint32_t bo = (bf) * 61440u; \
        _Pragma("unroll") \
        for (int t = 0; t < 12; t++) { \
            int idx = tid + (t << 8); \
            if (idx < 2048) { \
                int arr = idx >> 10, j = idx & 1023; \
                int row = j >> 2, ck = j & 3; \
                const __half* src = (arr ? g_wvl : g_wvh) + row * CC + (kc) + ck * 8; \
                cpasync16(sb + bo + arr * 20480u + row * 80 + ck * 16, src); \
            } else { \
                int j = idx - 2048; \
                int arr = j >> 9; j &= 511; \
                int row = j >> 2, ck = j & 3; \
                const __half* src = (arr ? g_xtl : g_xth) \
                    + (size_t)(b * NN + n0 + row) * CC + (kc) + ck * 8; \
                cpasync16(sb + bo + 40960u + arr * 10240u + row * 80 + ck * 16, src); \
            } \
        } \
        CP_COMMIT(); \
    } while (0)

    VF_FILL(0, 0);

    float acc[8][4][4];
#pragma unroll
    for (int mf = 0; mf < 8; mf++)
#pragma unroll
        for (int nf = 0; nf < 4; nf++)
#pragma unroll
            for (int e = 0; e < 4; e++) acc[mf][nf][e] = 0.f;

    for (int ch = 0; ch < 8; ch++) {
        CP_WAIT0();
        __syncthreads();
        if (ch + 1 < 8) VF_FILL((ch + 1) * 32, (ch + 1) & 1);
        const int bw = (ch & 1) * 15360;

#pragma unroll
        for (int ks = 0; ks < 2; ks++) {
            uint32_t bh[4][2], bl[4][2];
#pragma unroll
            for (int nf = 0; nf < 4; nf++) {
                int na = bw + 10240 + (wn * 32 + nf * 8 + r) * 20 + ks * 8 + q;
                bh[nf][0] = su[na];        bh[nf][1] = su[na + 4];
                bl[nf][0] = su[na + 2560]; bl[nf][1] = su[na + 2564];
            }
#pragma unroll
            for (int mf = 0; mf < 8; mf++) {
                int aa = bw + (wo * 128 + mf * 16 + r) * 20 + ks * 8 + q;
                uint32_t ah0 = su[aa], ah1 = su[aa + 160];
                uint32_t ah2 = su[aa + 4], ah3 = su[aa + 164];
                uint32_t al0 = su[aa + 5120], al1 = su[aa + 5280];
                uint32_t al2 = su[aa + 5124], al3 = su[aa + 5284];
#pragma unroll
                for (int nf = 0; nf < 4; nf++) {
                    mma_f16(acc[mf][nf], ah0, ah1, ah2, ah3, bh[nf][0], bh[nf][1]);
                    mma_f16(acc[mf][nf], ah0, ah1, ah2, ah3, bl[nf][0], bl[nf][1]);
                    mma_f16(acc[mf][nf], al0, al1, al2, al3, bh[nf][0], bh[nf][1]);
                }
            }
        }
        __syncthreads();
    }

#pragma unroll
    for (int mf = 0; mf < 8; mf++) {
#pragma unroll
        for (int er = 0; er < 2; er++) {
            const int c = wo * 128 + mf * 16 + er * 8 + r;
            float iv = s3[c] * rsqrtf(v3[c] + EPSBN);
            float off = b3[c] - m3[c] * iv;
#pragma unroll
            for (int nf = 0; nf < 4; nf++) {
                const int n = n0 + wn * 32 + nf * 8 + 2 * q;
                float y0 = fmaxf(fmaf(acc[mf][nf][er * 2 + 0], iv, off), 0.f);
                float y1 = fmaxf(fmaf(acc[mf][nf][er * 2 + 1], iv, off), 0.f);
                *reinterpret_cast<__half2*>(&g_vf[(size_t)(b * CC + c) * NN + n]) =
                    __floats2half2_rn(y0, y1);
            }
        }
    }
#undef VF_FILL
}

// ===========================================================================
// Flash attention fp16, 256 threads (8 warps), BN=64 keys/iter, ldmatrix.
// Warp: 16 rows x full 64 j x full 256 c. Register P, warp-local online max.
// Smem (bytes): QH[128][80]=10240, QL=10240, KH[64][80]x2=10240, KL=10240,
//               V[256][144]x2=73728. Total 114688.
// ===========================================================================
#define SQH 0
#define SQL 10240
#define SKH 20480
#define SKL 30720
#define SV  40960
#define FL_BYTES 114688

__global__ __launch_bounds__(256, 1)
void flash_f16_kernel(const float* __restrict__ x,
                      const float* __restrict__ gamma_p,
                      float* __restrict__ out)
{
    extern __shared__ char smc[];
    const uint32_t sb = smem_u32(smc);
    const uint32_t* qhw = reinterpret_cast<const uint32_t*>(smc + SQH);
    const uint32_t* qlw = reinterpret_cast<const uint32_t*>(smc + SQL);

    const int b   = blockIdx.y;
    const int i0  = blockIdx.x * 128;
    const int tid = threadIdx.x;
    const int w    = tid >> 5;
    const int lane = tid & 31;
    const int r    = lane >> 2;
    const int q    = lane & 3;
    const int row  = w * 16 + r;

    // ldmatrix lane geometry (validated in R14): 4 matrices = 2 row-octets x 2 k-halves
    const int lrow = ((lane >> 4) << 3) + (lane & 7);
    const int lko4 = ((lane >> 3) & 1) << 4;   // 16B k-half select
    const uint32_t kAddr0 = sb + SKH + (uint32_t)lrow * 80 + lko4;     // +10240 -> lo
    const uint32_t vAddr0 = sb + SV + (uint32_t)lrow * 144 + lko4;

#define FILL_KV(j0_, bf_) do { \
        _Pragma("unroll") \
        for (int tt = 0; tt < 2; tt++) { \
            int idx = tid + (tt << 8); \
            int split = idx >> 8, rem = idx & 255; \
            int j = rem >> 2, ck = rem & 3; \
            const __half* src = (split ? g_kfl : g_kfh) + (size_t)(b * NN + (j0_) + j) * DD + ck * 8; \
            cpasync16(sb + (split ? SKL : SKH) + (bf_) * 5120 + j * 80 + ck * 16, src); } \
        _Pragma("unroll") \
        for (int tt = 0; tt < 8; tt++) { \
            int idx = tid + (tt << 8); \
            int c = idx >> 3, ck = idx & 7; \
            const __half* src = g_vf + (size_t)(b * CC + c) * NN + (j0_) + ck * 8; \
            cpasync16(sb + SV + (bf_) * 36864 + c * 144 + ck * 16, src); } \
    } while (0)

    // Prologue: Q hi/lo [128][32]
    {
        const __half* qh = g_qfh + (size_t)(b * NN + i0) * DD;
        const __half* ql = g_qfl + (size_t)(b * NN + i0) * DD;
#pragma unroll
        for (int t = 0; t < 2; t++) {
            int idx = tid + (t << 8);
            int m = idx >> 2, ck = idx & 3;
            cpasync16(sb + SQH + m * 80 + ck * 16, qh + m * DD + ck * 8);
            cpasync16(sb + SQL + m * 80 + ck * 16, ql + m * DD + ck * 8);
        }
    }
    FILL_KV(0, 0);
    CP_COMMIT();
    CP_WAIT0();
    __syncthreads();

    // Q-hi fragments iter-invariant in registers; Q-lo reloaded per ch.
    uint32_t qa[2][4];
#pragma unroll
    for (int ch = 0; ch < 2; ch++) {
        int off = row * 20 + q + ch * 8;
        qa[ch][0] = qhw[off];       qa[ch][1] = qhw[off + 160];
        qa[ch][2] = qhw[off + 4];   qa[ch][3] = qhw[off + 164];
    }

    float oacc[32][4];
#pragma unroll
    for (int ct = 0; ct < 32; ct++)
#pragma unroll
        for (int e = 0; e < 4; e++) oacc[ct][e] = 0.f;
    float M0 = -1e30f, M1 = -1e30f, l0 = 0.f, l1 = 0.f;

    for (int t = 0; t < 64; t++) {
        const uint32_t kbf = (t & 1) * 5120;
        const uint32_t vbf = (t & 1) * 36864;

        if (t > 0) { CP_WAIT0(); __syncthreads(); }
        if (t + 1 < 64) { FILL_KV((t + 1) * 64, (t + 1) & 1); CP_COMMIT(); }

        // ---- Phase A: S[row..+16][0..64), 3-term fp16 compensation ----
        float sacc[8][4];
#pragma unroll
        for (int jt = 0; jt < 8; jt++)
#pragma unroll
            for (int e = 0; e < 4; e++) sacc[jt][e] = 0.f;

#pragma unroll
        for (int ch = 0; ch < 2; ch++) {
            int qoff = row * 20 + q + ch * 8;
            uint32_t qb0 = qlw[qoff], qb1 = qlw[qoff + 160];
            uint32_t qb2 = qlw[qoff + 4], qb3 = qlw[qoff + 164];
#pragma unroll
            for (int jt0 = 0; jt0 < 8; jt0 += 2) {
                uint32_t kh0, kh1, kh2, kh3, kl0, kl1, kl2, kl3;
                uint32_t ka = kAddr0 + kbf + (uint32_t)jt0 * 640 + ch * 32;
                ldsm_x4(kh0, kh1, kh2, kh3, ka);
                ldsm_x4(kl0, kl1, kl2, kl3, ka + 10240);
                mma_f16(sacc[jt0],     qa[ch][0], qa[ch][1], qa[ch][2], qa[ch][3], kh0, kh1);
                mma_f16(sacc[jt0],     qa[ch][0], qa[ch][1], qa[ch][2], qa[ch][3], kl0, kl1);
                mma_f16(sacc[jt0],     qb0, qb1, qb2, qb3, kh0, kh1);
                mma_f16(sacc[jt0 + 1], qa[ch][0], qa[ch][1], qa[ch][2], qa[ch][3], kh2, kh3);
                mma_f16(sacc[jt0 + 1], qa[ch][0], qa[ch][1], qa[ch][2], qa[ch][3], kl2, kl3);
                mma_f16(sacc[jt0 + 1], qb0, qb1, qb2, qb3, kh2, kh3);
            }
        }

        // ---- Online row max (warp-local) ----
        float mx0 = fmaxf(sacc[0][0], sacc[0][1]);
        float mx1 = fmaxf(sacc[0][2], sacc[0][3]);
#pragma unroll
        for (int jt = 1; jt < 8; jt++) {
            mx0 = fmaxf(mx0, fmaxf(sacc[jt][0], sacc[jt][1]));
            mx1 = fmaxf(mx1, fmaxf(sacc[jt][2], sacc[jt][3]));
        }
        mx0 = fmaxf(mx0, __shfl_xor_sync(0xFFFFFFFFu, mx0, 1));
        mx0 = fmaxf(mx0, __shfl_xor_sync(0xFFFFFFFFu, mx0, 2));
        mx1 = fmaxf(mx1, __shfl_xor_sync(0xFFFFFFFFu, mx1, 1));
        mx1 = fmaxf(mx1, __shfl_xor_sync(0xFFFFFFFFu, mx1, 2));
        float nm0 = fmaxf(M0, mx0), nm1 = fmaxf(M1, mx1);
        bool chg = (nm0 != M0) || (nm1 != M1);
        if (__any_sync(0xFFFFFFFFu, chg)) {
            float al0 = __expf(M0 - nm0), al1 = __expf(M1 - nm1);
            M0 = nm0; M1 = nm1;
            l0 *= al0; l1 *= al1;
#pragma unroll
            for (int ct = 0; ct < 32; ct++) {
                oacc[ct][0] *= al0; oacc[ct][1] *= al0;
                oacc[ct][2] *= al1; oacc[ct][3] *= al1;
            }
        }

        // ---- exp -> fp16 P fragments (registers), l partials ----
        uint32_t aP[4][4];
#pragma unroll
        for (int jc = 0; jc < 4; jc++) {
            const int t0 = 2 * jc, t1 = 2 * jc + 1;
            __half2 h0 = __floats2half2_rn(__expf(sacc[t0][0] - M0), __expf(sacc[t0][1] - M0));
            __half2 h1 = __floats2half2_rn(__expf(sacc[t0][2] - M1), __expf(sacc[t0][3] - M1));
            __half2 h2 = __floats2half2_rn(__expf(sacc[t1][0] - M0), __expf(sacc[t1][1] - M0));
            __half2 h3 = __floats2half2_rn(__expf(sacc[t1][2] - M1), __expf(sacc[t1][3] - M1));
            float2 f0 = __half22float2(h0), f1 = __half22float2(h1);
            float2 f2 = __half22float2(h2), f3 = __half22float2(h3);
            l0 += f0.x + f0.y + f2.x + f2.y;
            l1 += f1.x + f1.y + f3.x + f3.y;
            aP[jc][0] = *reinterpret_cast<uint32_t*>(&h0);
            aP[jc][1] = *reinterpret_cast<uint32_t*>(&h1);
            aP[jc][2] = *reinterpret_cast<uint32_t*>(&h2);
            aP[jc][3] = *reinterpret_cast<uint32_t*>(&h3);
        }

        // ---- Phase B: O[row..+16][0..256) += P * V (ldmatrix x4) ----
#pragma unroll
        for (int jc = 0; jc < 4; jc++) {
#pragma unroll
            for (int ct0 = 0; ct0 < 32; ct0 += 2) {
                uint32_t v0, v1, v2, v3;
                ldsm_x4(v0, v1, v2, v3, vAddr0 + vbf + (uint32_t)ct0 * 1152 + jc * 32);
                mma_f16(oacc[ct0],     aP[jc][0], aP[jc][1], aP[jc][2], aP[jc][3], v0, v1);
                mma_f16(oacc[ct0 + 1], aP[jc][0], aP[jc][1], aP[jc][2], aP[jc][3], v2, v3);
            }
        }
    }

    // ---- Final l reduction across quad lanes ----
    l0 += __shfl_xor_sync(0xFFFFFFFFu, l0, 1);
    l0 += __shfl_xor_sync(0xFFFFFFFFu, l0, 2);
    l1 += __shfl_xor_sync(0xFFFFFFFFu, l1, 1);
    l1 += __shfl_xor_sync(0xFFFFFFFFu, l1, 2);

    const float gam = gamma_p[0];
    const float s0 = gam / l0, s1 = gam / l1;
    const int mrow0 = i0 + row;
    const int mrow1 = mrow0 + 8;
#pragma unroll
    for (int ct = 0; ct < 32; ct++) {
        const int c0 = ct * 8 + 2 * q;
        size_t g00 = (size_t)(b * CC + c0) * NN + mrow0;
        size_t g01 = (size_t)(b * CC + c0 + 1) * NN + mrow0;
        size_t g10 = (size_t)(b * CC + c0) * NN + mrow1;
        size_t g11 = (size_t)(b * CC + c0 + 1) * NN + mrow1;
        out[g00] = fmaf(oacc[ct][0], s0, x[g00]);
        out[g01] = fmaf(oacc[ct][1], s0, x[g01]);
        out[g10] = fmaf(oacc[ct][2], s1, x[g10]);
        out[g11] = fmaf(oacc[ct][3], s1, x[g11]);
    }
#undef FILL_KV
}

// ===========================================================================
extern "C" void kernel_launch(void* const* d_in, const int* in_sizes, int n_in,
                              void* d_out, int out_size)
{
    const float* x   = (const float*)d_in[0];
    const float* w_q = (const float*)d_in[1];
    const float* w_k = (const float*)d_in[2];
    const float* w_v = (const float*)d_in[3];
    const float* s1 = (const float*)d_in[4];
    const float* b1 = (const float*)d_in[5];
    const float* m1 = (const float*)d_in[6];
    const float* v1 = (const float*)d_in[7];
    const float* s2 = (const float*)d_in[8];
    const float* b2 = (const float*)d_in[9];
    const float* m2 = (const float*)d_in[10];
    const float* v2 = (const float*)d_in[11];
    const float* s3 = (const float*)d_in[12];
    const float* b3 = (const float*)d_in[13];
    const float* m3 = (const float*)d_in[14];
    const float* v3 = (const float*)d_in[15];
    const float* gamma = (const float*)d_in[16];
    float* out = (float*)d_out;

    cudaFuncSetAttribute(qk_proj_f16_kernel, cudaFuncAttributeMaxDynamicSharedMemorySize, QKP_SMB);
    cudaFuncSetAttribute(v_proj_f16_kernel,  cudaFuncAttributeMaxDynamicSharedMemorySize, VP_SMB);
    cudaFuncSetAttribute(flash_f16_kernel,   cudaFuncAttributeMaxDynamicSharedMemorySize, FL_BYTES);

    split_xt_kernel<<<dim3(NN / 64, CC / 64, BB), 256>>>(x);
    split_w_f16_kernel<<<(CC * CC + 64 * CC) / 256, 256>>>(w_q, w_k, w_v);
    qk_proj_f16_kernel<<<dim3(NN / 256, BB), 256, QKP_SMB>>>(
        s1, b1, m1, v1, s2, b2, m2, v2);
    v_proj_f16_kernel<<<dim3(NN / 128, BB), 256, VP_SMB>>>(s3, b3, m3, v3);
    flash_f16_kernel<<<dim3(NN / 128, BB), 256, FL_BYTES>>>(x, gamma, out);
}

// round 17
// speedup vs baseline: 1.4039x; 1.0701x over previous
#include <cuda_runtime.h>
#include <cuda_fp16.h>
#include <cstdint>

#define BB 4
#define CC 256
#define NN 4096
#define DD 32
#define EPSBN 1e-5f
#define LOG2E 1.4426950408889634f

// Scratch (device globals; no allocation)
__device__ __align__(16) __half g_xth[BB * NN * CC];   // x^T hi [b][n][c]
__device__ __align__(16) __half g_xtl[BB * NN * CC];   // x^T lo
__device__ __align__(16) __half g_wvh[CC * CC];        // w_v hi [o][c]
__device__ __align__(16) __half g_wqkh[64 * CC];       // rows 0..31 wq, 32..63 wk
__device__ __align__(16) __half g_wqkl[64 * CC];
// fp16 flash inputs
__device__ __align__(16) __half g_qfh[BB * NN * DD];   // [b][n][d]
__device__ __align__(16) __half g_qfl[BB * NN * DD];
__device__ __align__(16) __half g_kfh[BB * NN * DD];   // [b][n][d]
__device__ __align__(16) __half g_kfl[BB * NN * DD];
__device__ __align__(16) __half g_vf [BB * CC * NN];   // [b][c][n]

// ===========================================================================
// Helpers
// ===========================================================================
__device__ __forceinline__ void h_split(float y, __half& h, __half& l) {
    h = __float2half_rn(y);
    l = __float2half_rn(y - __half2float(h));
}
__device__ __forceinline__ void cpasync16(uint32_t dst, const void* src) {
    asm volatile("cp.async.cg.shared.global [%0], [%1], 16;" :: "r"(dst), "l"(src));
}
#define CP_COMMIT() asm volatile("cp.async.commit_group;" ::: "memory")
#define CP_WAIT0()  asm volatile("cp.async.wait_group 0;" ::: "memory")
__device__ __forceinline__ uint32_t smem_u32(const void* p) {
    uint32_t a;
    asm("{ .reg .u64 t; cvta.to.shared.u64 t, %1; cvt.u32.u64 %0, t; }" : "=r"(a) : "l"(p));
    return a;
}
__device__ __forceinline__ void mma_f16(float* d,
                                        uint32_t a0, uint32_t a1, uint32_t a2, uint32_t a3,
                                        uint32_t b0, uint32_t b1) {
    asm volatile(
        "mma.sync.aligned.m16n8k16.row.col.f32.f16.f16.f32 "
        "{%0,%1,%2,%3}, {%4,%5,%6,%7}, {%8,%9}, {%0,%1,%2,%3};"
        : "+f"(d[0]), "+f"(d[1]), "+f"(d[2]), "+f"(d[3])
        : "r"(a0), "r"(a1), "r"(a2), "r"(a3), "r"(b0), "r"(b1));
}
__device__ __forceinline__ void ldsm_x4(uint32_t& r0, uint32_t& r1,
                                        uint32_t& r2, uint32_t& r3, uint32_t addr) {
    asm volatile("ldmatrix.sync.aligned.m8n8.x4.shared.b16 {%0,%1,%2,%3}, [%4];"
                 : "=r"(r0), "=r"(r1), "=r"(r2), "=r"(r3) : "r"(addr));
}
__device__ __forceinline__ uint32_t ex2_f16x2(float e0, float e1) {
    __half2 h = __floats2half2_rn(e0, e1);
    uint32_t r;
    asm("ex2.approx.f16x2 %0, %1;" : "=r"(r) : "r"(*reinterpret_cast<uint32_t*>(&h)));
    return r;
}

// ===========================================================================
// split_xt: x [b][c][n] fp32 -> x^T hi/lo fp16 [b][n][c]. Tiled transpose.
// ===========================================================================
__global__ __launch_bounds__(256) void split_xt_kernel(const float* __restrict__ x) {
    __shared__ __half shh[64][65];
    __shared__ __half shl[64][65];
    const int b  = blockIdx.z;
    const int c0 = blockIdx.y * 64;
    const int n0 = blockIdx.x * 64;
    const int tid = threadIdx.x;
    {
        int c = tid >> 2, ng = tid & 3;
#pragma unroll
        for (int i = 0; i < 4; i++) {
            int n = ng * 16 + i * 4;
            float4 v = *reinterpret_cast<const float4*>(
                x + (size_t)(b * CC + c0 + c) * NN + n0 + n);
            h_split(v.x, shh[c][n + 0], shl[c][n + 0]);
            h_split(v.y, shh[c][n + 1], shl[c][n + 1]);
            h_split(v.z, shh[c][n + 2], shl[c][n + 2]);
            h_split(v.w, shh[c][n + 3], shl[c][n + 3]);
        }
    }
    __syncthreads();
    {
        int n = tid >> 2, cg = tid & 3;
        __half bh[16], bl[16];
#pragma unroll
        for (int j = 0; j < 16; j++) {
            bh[j] = shh[cg * 16 + j][n];
            bl[j] = shl[cg * 16 + j][n];
        }
        size_t base = (size_t)(b * NN + n0 + n) * CC + c0 + cg * 16;
        reinterpret_cast<uint4*>(g_xth + base)[0] = reinterpret_cast<uint4*>(bh)[0];
        reinterpret_cast<uint4*>(g_xth + base)[1] = reinterpret_cast<uint4*>(bh)[1];
        reinterpret_cast<uint4*>(g_xtl + base)[0] = reinterpret_cast<uint4*>(bl)[0];
        reinterpret_cast<uint4*>(g_xtl + base)[1] = reinterpret_cast<uint4*>(bl)[1];
    }
}

// ===========================================================================
// split_w_f16: weights -> fp16 (w_v hi only; wqk hi/lo).
// ===========================================================================
__global__ __launch_bounds__(256) void split_w_f16_kernel(
    const float* __restrict__ w_q, const float* __restrict__ w_k,
    const float* __restrict__ w_v)
{
    int idx = blockIdx.x * 256 + threadIdx.x;
    if (idx < CC * CC) {
        g_wvh[idx] = __float2half_rn(w_v[idx]);
    } else {
        int j = idx - CC * CC;
        int o = j >> 8, c = j & 255;
        float v = (o < 32) ? w_q[o * CC + c] : w_k[(o - 32) * CC + c];
        __half h, l; h_split(v, h, l);
        g_wqkh[j] = h; g_wqkl[j] = l;
    }
}

// ===========================================================================
// qk projection, fp16 3-term compensated mma. (unchanged, proven)
// ===========================================================================
#define QKP_SMB 102400

__global__ __launch_bounds__(256, 1) void qk_proj_f16_kernel(
    const float* __restrict__ s1, const float* __restrict__ b1,
    const float* __restrict__ m1, const float* __restrict__ v1,
    const float* __restrict__ s2, const float* __restrict__ b2,
    const float* __restrict__ m2, const float* __restrict__ v2)
{
    extern __shared__ char smc[];
    const uint32_t sb = smem_u32(smc);
    const uint32_t* su = reinterpret_cast<const uint32_t*>(smc);
    __half* st = reinterpret_cast<__half*>(smc);

    const int b  = blockIdx.y;
    const int n0 = blockIdx.x * 256;
    const int tid = threadIdx.x;
    const int w = tid >> 5, lane = tid & 31;
    const int r = lane >> 2, q = lane & 3;

#define QKF_FILL(kc, bf) do { \
        const uint32_t bo = (bf) * 51200u; \
        _Pragma("unroll") \
        for (int t = 0; t < 10; t++) { \
            int idx = tid + (t << 8); \
            if (idx < 512) { \
                int arr = idx >> 8, j = idx & 255; \
                int row = j >> 2, ck = j & 3; \
                const __half* src = (arr ? g_wqkl : g_wqkh) + row * CC + (kc) + ck * 8; \
                cpasync16(sb + bo + arr * 5120u + row * 80 + ck * 16, src); \
            } else { \
                int j = idx - 512; \
                int arr = j >> 10; j &= 1023; \
                int row = j >> 2, ck = j & 3; \
                const __half* src = (arr ? g_xtl : g_xth) \
                    + (size_t)(b * NN + n0 + row) * CC + (kc) + ck * 8; \
                cpasync16(sb + bo + 10240u + arr * 20480u + row * 80 + ck * 16, src); \
            } \
        } \
        CP_COMMIT(); \
    } while (0)

    QKF_FILL(0, 0);

    float acc[4][4][4];
#pragma unroll
    for (int mf = 0; mf < 4; mf++)
#pragma unroll
        for (int nf = 0; nf < 4; nf++)
#pragma unroll
            for (int e = 0; e < 4; e++) acc[mf][nf][e] = 0.f;

    for (int ch = 0; ch < 8; ch++) {
        CP_WAIT0();
        __syncthreads();
        if (ch + 1 < 8) QKF_FILL((ch + 1) * 32, (ch + 1) & 1);
        const int bw = (ch & 1) * 12800;

#pragma unroll
        for (int ks = 0; ks < 2; ks++) {
            uint32_t bh[4][2], bl[4][2];
#pragma unroll
            for (int nf = 0; nf < 4; nf++) {
                int na = bw + 2560 + (w * 32 + nf * 8 + r) * 20 + ks * 8 + q;
                bh[nf][0] = su[na];        bh[nf][1] = su[na + 4];
                bl[nf][0] = su[na + 5120]; bl[nf][1] = su[na + 5124];
            }
#pragma unroll
            for (int mf = 0; mf < 4; mf++) {
                int aa = bw + (mf * 16 + r) * 20 + ks * 8 + q;
                uint32_t ah0 = su[aa], ah1 = su[aa + 160];
                uint32_t ah2 = su[aa + 4], ah3 = su[aa + 164];
                uint32_t al0 = su[aa + 1280], al1 = su[aa + 1440];
                uint32_t al2 = su[aa + 1284], al3 = su[aa + 1444];
#pragma unroll
                for (int nf = 0; nf < 4; nf++) {
                    mma_f16(acc[mf][nf], ah0, ah1, ah2, ah3, bh[nf][0], bh[nf][1]);
                    mma_f16(acc[mf][nf], ah0, ah1, ah2, ah3, bl[nf][0], bl[nf][1]);
                    mma_f16(acc[mf][nf], al0, al1, al2, al3, bh[nf][0], bh[nf][1]);
                }
            }
        }
        __syncthreads();
    }

#pragma unroll
    for (int mf = 0; mf < 4; mf++) {
        const int isK = mf >> 1;
#pragma unroll
        for (int er = 0; er < 2; er++) {
            const int d = (mf & 1) * 16 + er * 8 + r;
            float iv, off;
            if (!isK) { iv = s1[d] * rsqrtf(v1[d] + EPSBN); off = b1[d] - m1[d] * iv; }
            else      { iv = s2[d] * rsqrtf(v2[d] + EPSBN); off = b2[d] - m2[d] * iv; }
            const int hb = isK ? 16384 : 0;
#pragma unroll
            for (int nf = 0; nf < 4; nf++) {
                const int n = w * 32 + nf * 8 + 2 * q;
                float y0 = fmaxf(fmaf(acc[mf][nf][er * 2 + 0], iv, off), 0.f);
                float y1 = fmaxf(fmaf(acc[mf][nf][er * 2 + 1], iv, off), 0.f);
                __half h0, l0, h1, l1;
                h_split(y0, h0, l0);
                h_split(y1, h1, l1);
                st[hb + n * 32 + d] = h0;        st[hb + (n + 1) * 32 + d] = h1;
                st[hb + 8192 + n * 32 + d] = l0; st[hb + 8192 + (n + 1) * 32 + d] = l1;
            }
        }
    }
    __syncthreads();
    {
        __half* gp[4] = { g_qfh, g_qfl, g_kfh, g_kfl };
        const int n = tid;
#pragma unroll
        for (int arr = 0; arr < 4; arr++) {
            const uint4* src = reinterpret_cast<const uint4*>(st + arr * 8192 + n * 32);
            uint4* dst = reinterpret_cast<uint4*>(gp[arr] + (size_t)(b * NN + n0 + n) * DD);
#pragma unroll
            for (int j = 0; j < 4; j++) dst[j] = src[j];
        }
    }
#undef QKF_FILL
}

// ===========================================================================
// v projection, fp16 2-term (w-hi only: y = wh*xh + wh*xl). fp16 out [b][c][n].
// grid (32, 4), 256 threads. Smem/buffer: WH 20480 + XH 10240 + XL 10240
// = 40960, x2 = 81920 B.
// ===========================================================================
#define VP_SMB 81920

__global__ __launch_bounds__(256, 1) void v_proj_f16_kernel(
    const float* __restrict__ s3, const float* __restrict__ b3,
    const float* __restrict__ m3, const float* __restrict__ v3)
{
    extern __shared__ char smc[];
    const uint32_t sb = smem_u32(smc);
    const uint32_t* su = reinterpret_cast<const uint32_t*>(smc);

    const int b  = blockIdx.y;
    const int n0 = blockIdx.x * 128;
    const int tid = threadIdx.x;
    const int w = tid >> 5, lane = tid & 31;
    const int wo = w >> 2, wn = w & 3;
    const int r = lane >> 2, q = lane & 3;

#define VF_FILL(kc, bf) do { \
        const uint32_t bo = (bf) * 40960u; \
        _Pragma("unroll") \
        for (int t = 0; t < 8; t++) { \
            int idx = tid + (t << 8); \
            if (idx < 1024) { \
                int row = idx >> 2, ck = idx & 3; \
                const __half* src = g_wvh + row * CC + (kc) + ck * 8; \
                cpasync16(sb + bo + row * 80 + ck * 16, src); \
            } else { \
                int j = idx - 1024; \
                int arr = j >> 9; j &= 511; \
                int row = j >> 2, ck = j & 3; \
                const __half* src = (arr ? g_xtl : g_xth) \
                    + (size_t)(b * NN + n0 + row) * CC + (kc) + ck * 8; \
                cpasync16(sb + bo + 20480u + arr * 10240u + row * 80 + ck * 16, src); \
            } \
        } \
        CP_COMMIT(); \
    } while (0)

    VF_FILL(0, 0);

    float acc[8][4][4];
#pragma unroll
    for (int mf = 0; mf < 8; mf++)
#pragma unroll
        for (int nf = 0; nf < 4; nf++)
#pragma unroll
            for (int e = 0; e < 4; e++) acc[mf][nf][e] = 0.f;

    for (int ch = 0; ch < 8; ch++) {
        CP_WAIT0();
        __syncthreads();
        if (ch + 1 < 8) VF_FILL((ch + 1) * 32, (ch + 1) & 1);
        const int bw = (ch & 1) * 10240;   // words

#pragma unroll
        for (int ks = 0; ks < 2; ks++) {
            uint32_t bh[4][2], bl[4][2];
#pragma unroll
            for (int nf = 0; nf < 4; nf++) {
                int na = bw + 5120 + (wn * 32 + nf * 8 + r) * 20 + ks * 8 + q;
                bh[nf][0] = su[na];        bh[nf][1] = su[na + 4];
                bl[nf][0] = su[na + 2560]; bl[nf][1] = su[na + 2564];
            }
#pragma unroll
            for (int mf = 0; mf < 8; mf++) {
                int aa = bw + (wo * 128 + mf * 16 + r) * 20 + ks * 8 + q;
                uint32_t ah0 = su[aa], ah1 = su[aa + 160];
                uint32_t ah2 = su[aa + 4], ah3 = su[aa + 164];
#pragma unroll
                for (int nf = 0; nf < 4; nf++) {
                    mma_f16(acc[mf][nf], ah0, ah1, ah2, ah3, bh[nf][0], bh[nf][1]);
                    mma_f16(acc[mf][nf], ah0, ah1, ah2, ah3, bl[nf][0], bl[nf][1]);
                }
            }
        }
        __syncthreads();
    }

#pragma unroll
    for (int mf = 0; mf < 8; mf++) {
#pragma unroll
        for (int er = 0; er < 2; er++) {
            const int c = wo * 128 + mf * 16 + er * 8 + r;
            float iv = s3[c] * rsqrtf(v3[c] + EPSBN);
            float off = b3[c] - m3[c] * iv;
#pragma unroll
            for (int nf = 0; nf < 4; nf++) {
                const int n = n0 + wn * 32 + nf * 8 + 2 * q;
                float y0 = fmaxf(fmaf(acc[mf][nf][er * 2 + 0], iv, off), 0.f);
                float y1 = fmaxf(fmaf(acc[mf][nf][er * 2 + 1], iv, off), 0.f);
                *reinterpret_cast<__half2*>(&g_vf[(size_t)(b * CC + c) * NN + n]) =
                    __floats2half2_rn(y0, y1);
            }
        }
    }
#undef VF_FILL
}

// ===========================================================================
// Flash attention fp16, 256 threads, BN=64, ldmatrix, ex2.f16x2 softmax.
// Smem: QH 10240, QL 10240, KH 10240x?... layout as R16: 114688 B.
// ===========================================================================
#define SQH 0
#define SQL 10240
#define SKH 20480
#define SKL 30720
#define SV  40960
#define FL_BYTES 114688

__global__ __launch_bounds__(256, 1)
void flash_f16_kernel(const float* __restrict__ x,
                      const float* __restrict__ gamma_p,
                      float* __restrict__ out)
{
    extern __shared__ char smc[];
    const uint32_t sb = smem_u32(smc);
    const uint32_t* qhw = reinterpret_cast<const uint32_t*>(smc + SQH);
    const uint32_t* qlw = reinterpret_cast<const uint32_t*>(smc + SQL);

    const int b   = blockIdx.y;
    const int i0  = blockIdx.x * 128;
    const int tid = threadIdx.x;
    const int w    = tid >> 5;
    const int lane = tid & 31;
    const int r    = lane >> 2;
    const int q    = lane & 3;
    const int row  = w * 16 + r;

    const int lrow = ((lane >> 4) << 3) + (lane & 7);
    const int lko4 = ((lane >> 3) & 1) << 4;
    const uint32_t kAddr0 = sb + SKH + (uint32_t)lrow * 80 + lko4;     // +10240 -> lo
    const uint32_t vAddr0 = sb + SV + (uint32_t)lrow * 144 + lko4;

#define FILL_KV(j0_, bf_) do { \
        _Pragma("unroll") \
        for (int tt = 0; tt < 2; tt++) { \
            int idx = tid + (tt << 8); \
            int split = idx >> 8, rem = idx & 255; \
            int j = rem >> 2, ck = rem & 3; \
            const __half* src = (split ? g_kfl : g_kfh) + (size_t)(b * NN + (j0_) + j) * DD + ck * 8; \
            cpasync16(sb + (split ? SKL : SKH) + (bf_) * 5120 + j * 80 + ck * 16, src); } \
        _Pragma("unroll") \
        for (int tt = 0; tt < 8; tt++) { \
            int idx = tid + (tt << 8); \
            int c = idx >> 3, ck = idx & 7; \
            const __half* src = g_vf + (size_t)(b * CC + c) * NN + (j0_) + ck * 8; \
            cpasync16(sb + SV + (bf_) * 36864 + c * 144 + ck * 16, src); } \
    } while (0)

    // Prologue: Q hi/lo [128][32]
    {
        const __half* qh = g_qfh + (size_t)(b * NN + i0) * DD;
        const __half* ql = g_qfl + (size_t)(b * NN + i0) * DD;
#pragma unroll
        for (int t = 0; t < 2; t++) {
            int idx = tid + (t << 8);
            int m = idx >> 2, ck = idx & 3;
            cpasync16(sb + SQH + m * 80 + ck * 16, qh + m * DD + ck * 8);
            cpasync16(sb + SQL + m * 80 + ck * 16, ql + m * DD + ck * 8);
        }
    }
    FILL_KV(0, 0);
    CP_COMMIT();
    CP_WAIT0();
    __syncthreads();

    // Q hi AND lo fragments iter-invariant in registers.
    uint32_t qa[2][4], qb[2][4];
#pragma unroll
    for (int ch = 0; ch < 2; ch++) {
        int off = row * 20 + q + ch * 8;
        qa[ch][0] = qhw[off];       qa[ch][1] = qhw[off + 160];
        qa[ch][2] = qhw[off + 4];   qa[ch][3] = qhw[off + 164];
        qb[ch][0] = qlw[off];       qb[ch][1] = qlw[off + 160];
        qb[ch][2] = qlw[off + 4];   qb[ch][3] = qlw[off + 164];
    }

    float oacc[32][4];
#pragma unroll
    for (int ct = 0; ct < 32; ct++)
#pragma unroll
        for (int e = 0; e < 4; e++) oacc[ct][e] = 0.f;
    float M0 = -1e30f, M1 = -1e30f, l0 = 0.f, l1 = 0.f;

    for (int t = 0; t < 64; t++) {
        const uint32_t kbf = (t & 1) * 5120;
        const uint32_t vbf = (t & 1) * 36864;

        if (t > 0) { CP_WAIT0(); __syncthreads(); }
        if (t + 1 < 64) { FILL_KV((t + 1) * 64, (t + 1) & 1); CP_COMMIT(); }

        // ---- Phase A: S[row..+16][0..64), 3-term fp16 compensation ----
        float sacc[8][4];
#pragma unroll
        for (int jt = 0; jt < 8; jt++)
#pragma unroll
            for (int e = 0; e < 4; e++) sacc[jt][e] = 0.f;

#pragma unroll
        for (int ch = 0; ch < 2; ch++) {
#pragma unroll
            for (int jt0 = 0; jt0 < 8; jt0 += 2) {
                uint32_t kh0, kh1, kh2, kh3, kl0, kl1, kl2, kl3;
                uint32_t ka = kAddr0 + kbf + (uint32_t)jt0 * 640 + ch * 32;
                ldsm_x4(kh0, kh1, kh2, kh3, ka);
                ldsm_x4(kl0, kl1, kl2, kl3, ka + 10240);
                mma_f16(sacc[jt0],     qa[ch][0], qa[ch][1], qa[ch][2], qa[ch][3], kh0, kh1);
                mma_f16(sacc[jt0],     qa[ch][0], qa[ch][1], qa[ch][2], qa[ch][3], kl0, kl1);
                mma_f16(sacc[jt0],     qb[ch][0], qb[ch][1], qb[ch][2], qb[ch][3], kh0, kh1);
                mma_f16(sacc[jt0 + 1], qa[ch][0], qa[ch][1], qa[ch][2], qa[ch][3], kh2, kh3);
                mma_f16(sacc[jt0 + 1], qa[ch][0], qa[ch][1], qa[ch][2], qa[ch][3], kl2, kl3);
                mma_f16(sacc[jt0 + 1], qb[ch][0], qb[ch][1], qb[ch][2], qb[ch][3], kh2, kh3);
            }
        }

        // ---- Online row max (warp-local) ----
        float mx0 = fmaxf(sacc[0][0], sacc[0][1]);
        float mx1 = fmaxf(sacc[0][2], sacc[0][3]);
#pragma unroll
        for (int jt = 1; jt < 8; jt++) {
            mx0 = fmaxf(mx0, fmaxf(sacc[jt][0], sacc[jt][1]));
            mx1 = fmaxf(mx1, fmaxf(sacc[jt][2], sacc[jt][3]));
        }
        mx0 = fmaxf(mx0, __shfl_xor_sync(0xFFFFFFFFu, mx0, 1));
        mx0 = fmaxf(mx0, __shfl_xor_sync(0xFFFFFFFFu, mx0, 2));
        mx1 = fmaxf(mx1, __shfl_xor_sync(0xFFFFFFFFu, mx1, 1));
        mx1 = fmaxf(mx1, __shfl_xor_sync(0xFFFFFFFFu, mx1, 2));
        float nm0 = fmaxf(M0, mx0), nm1 = fmaxf(M1, mx1);
        bool chg = (nm0 != M0) || (nm1 != M1);
        if (__any_sync(0xFFFFFFFFu, chg)) {
            float al0 = __expf(M0 - nm0), al1 = __expf(M1 - nm1);
            M0 = nm0; M1 = nm1;
            l0 *= al0; l1 *= al1;
#pragma unroll
            for (int ct = 0; ct < 32; ct++) {
                oacc[ct][0] *= al0; oacc[ct][1] *= al0;
                oacc[ct][2] *= al1; oacc[ct][3] *= al1;
            }
        }

        // ---- Per j-chunk: exponent (fp32 FFMA) -> ex2.f16x2 -> P frags,
        //      issue PhaseB mmas, then l accumulation (overlaps tensor) ----
        const float c0 = -M0 * LOG2E, c1 = -M1 * LOG2E;
#pragma unroll
        for (int jc = 0; jc < 4; jc++) {
            const int t0 = 2 * jc, t1 = t0 + 1;
            uint32_t p0 = ex2_f16x2(fmaf(sacc[t0][0], LOG2E, c0), fmaf(sacc[t0][1], LOG2E, c0));
            uint32_t p1 = ex2_f16x2(fmaf(sacc[t0][2], LOG2E, c1), fmaf(sacc[t0][3], LOG2E, c1));
            uint32_t p2 = ex2_f16x2(fmaf(sacc[t1][0], LOG2E, c0), fmaf(sacc[t1][1], LOG2E, c0));
            uint32_t p3 = ex2_f16x2(fmaf(sacc[t1][2], LOG2E, c1), fmaf(sacc[t1][3], LOG2E, c1));

#pragma unroll
            for (int ct0 = 0; ct0 < 32; ct0 += 2) {
                uint32_t v0, v1, v2, v3;
                ldsm_x4(v0, v1, v2, v3, vAddr0 + vbf + (uint32_t)ct0 * 1152 + jc * 32);
                mma_f16(oacc[ct0],     p0, p1, p2, p3, v0, v1);
                mma_f16(oacc[ct0 + 1], p0, p1, p2, p3, v2, v3);
            }

            float2 f0 = __half22float2(*reinterpret_cast<__half2*>(&p0));
            float2 f1 = __half22float2(*reinterpret_cast<__half2*>(&p1));
            float2 f2 = __half22float2(*reinterpret_cast<__half2*>(&p2));
            float2 f3 = __half22float2(*reinterpret_cast<__half2*>(&p3));
            l0 += f0.x + f0.y + f2.x + f2.y;
            l1 += f1.x + f1.y + f3.x + f3.y;
        }
    }

    // ---- Final l reduction across quad lanes ----
    l0 += __shfl_xor_sync(0xFFFFFFFFu, l0, 1);
    l0 += __shfl_xor_sync(0xFFFFFFFFu, l0, 2);
    l1 += __shfl_xor_sync(0xFFFFFFFFu, l1, 1);
    l1 += __shfl_xor_sync(0xFFFFFFFFu, l1, 2);

    const float gam = gamma_p[0];
    const float s0 = gam / l0, s1 = gam / l1;
    const int mrow0 = i0 + row;
    const int mrow1 = mrow0 + 8;
#pragma unroll
    for (int ct = 0; ct < 32; ct++) {
        const int c0i = ct * 8 + 2 * q;
        size_t g00 = (size_t)(b * CC + c0i) * NN + mrow0;
        size_t g01 = (size_t)(b * CC + c0i + 1) * NN + mrow0;
        size_t g10 = (size_t)(b * CC + c0i) * NN + mrow1;
        size_t g11 = (size_t)(b * CC + c0i + 1) * NN + mrow1;
        out[g00] = fmaf(oacc[ct][0], s0, x[g00]);
        out[g01] = fmaf(oacc[ct][1], s0, x[g01]);
        out[g10] = fmaf(oacc[ct][2], s1, x[g10]);
        out[g11] = fmaf(oacc[ct][3], s1, x[g11]);
    }
#undef FILL_KV
}

// ===========================================================================
extern "C" void kernel_launch(void* const* d_in, const int* in_sizes, int n_in,
                              void* d_out, int out_size)
{
    const float* x   = (const float*)d_in[0];
    const float* w_q = (const float*)d_in[1];
    const float* w_k = (const float*)d_in[2];
    const float* w_v = (const float*)d_in[3];
    const float* s1 = (const float*)d_in[4];
    const float* b1 = (const float*)d_in[5];
    const float* m1 = (const float*)d_in[6];
    const float* v1 = (const float*)d_in[7];
    const float* s2 = (const float*)d_in[8];
    const float* b2 = (const float*)d_in[9];
    const float* m2 = (const float*)d_in[10];
    const float* v2 = (const float*)d_in[11];
    const float* s3 = (const float*)d_in[12];
    const float* b3 = (const float*)d_in[13];
    const float* m3 = (const float*)d_in[14];
    const float* v3 = (const float*)d_in[15];
    const float* gamma = (const float*)d_in[16];
    float* out = (float*)d_out;

    cudaFuncSetAttribute(qk_proj_f16_kernel, cudaFuncAttributeMaxDynamicSharedMemorySize, QKP_SMB);
    cudaFuncSetAttribute(v_proj_f16_kernel,  cudaFuncAttributeMaxDynamicSharedMemorySize, VP_SMB);
    cudaFuncSetAttribute(flash_f16_kernel,   cudaFuncAttributeMaxDynamicSharedMemorySize, FL_BYTES);

    split_xt_kernel<<<dim3(NN / 64, CC / 64, BB), 256>>>(x);
    split_w_f16_kernel<<<(CC * CC + 64 * CC) / 256, 256>>>(w_q, w_k, w_v);
    qk_proj_f16_kernel<<<dim3(NN / 256, BB), 256, QKP_SMB>>>(
        s1, b1, m1, v1, s2, b2, m2, v2);
    v_proj_f16_kernel<<<dim3(NN / 128, BB), 256, VP_SMB>>>(s3, b3, m3, v3);
    flash_f16_kernel<<<dim3(NN / 128, BB), 256, FL_BYTES>>>(x, gamma, out);
}